// round 5
// baseline (speedup 1.0000x reference)
#include <cuda_runtime.h>
#include <cuda_bf16.h>

#define N_ITEMS 100000
#define HID 128
#define NNZ_N 1600000
#define RPB 8      // output rows per spmm block (100000 % 8 == 0)
#define CH 256     // edge staging chunk

// Intermediate: support = X @ W^T + b   (51.2 MB device-global scratch)
__device__ float g_support[(size_t)N_ITEMS * HID];

// Packed fp32x2 FMA (2 FMAs / instruction on the fma pipe).
__device__ __forceinline__ unsigned long long ffma2(unsigned long long a,
                                                    unsigned long long b,
                                                    unsigned long long c) {
    unsigned long long d;
    asm("fma.rn.f32x2 %0, %1, %2, %3;" : "=l"(d) : "l"(a), "l"(b), "l"(c));
    return d;
}

// ---------------------------------------------------------------------------
// GEMM: support[n][c] = sum_k X[n][k] * W[c][k] + bias[c]
// Tile: 128 rows x 128 cols per block, 256 threads, 8x8 register tile/thread.
// Packing is along K: acc holds {even-k partial, odd-k partial}; both operand
// k-pairs are contiguous in memory -> plain LDS.64, no repack instructions.
// ---------------------------------------------------------------------------
extern "C" __global__ void __launch_bounds__(256)
gemm_kernel(const float* __restrict__ X, const float* __restrict__ W,
            const float* __restrict__ bias, int nrows)
{
    extern __shared__ unsigned long long smem[];
    unsigned long long* xs = smem;             // [64 k-pairs][128 rows]
    unsigned long long* ws = smem + 64 * 128;  // [64 k-pairs][128 cols]

    const int tid  = threadIdx.x;
    const int row0 = blockIdx.x * 128;

    // Fill: thread t owns tile row/col r = t/2, k4 range selected by t&1.
    // STS pattern is conflict-free (adjacent lanes -> adjacent 8B in r).
    {
        const int r      = tid >> 1;
        const int k4base = (tid & 1) * 16;
        const int grow   = row0 + r;
        const bool xok   = grow < nrows;
        const float4* xr4 = (const float4*)(X + (size_t)grow * HID);
        const float4* wr4 = (const float4*)(W + (size_t)r * HID);
        #pragma unroll
        for (int j = 0; j < 16; j++) {
            int k4 = k4base + j;
            float4 xv = xok ? xr4[k4] : make_float4(0.f, 0.f, 0.f, 0.f);
            float4 wv = wr4[k4];
            float2 x0 = make_float2(xv.x, xv.y);
            float2 x1 = make_float2(xv.z, xv.w);
            float2 w0 = make_float2(wv.x, wv.y);
            float2 w1 = make_float2(wv.z, wv.w);
            xs[(2 * k4)     * 128 + r] = *(unsigned long long*)&x0;
            xs[(2 * k4 + 1) * 128 + r] = *(unsigned long long*)&x1;
            ws[(2 * k4)     * 128 + r] = *(unsigned long long*)&w0;
            ws[(2 * k4 + 1) * 128 + r] = *(unsigned long long*)&w1;
        }
    }
    __syncthreads();

    const int tx = tid & 15;   // col group: c = tx + 16*j  (contiguous per warp)
    const int ty = tid >> 4;   // row group: r = ty*8 + i   (broadcast per warp)

    unsigned long long acc[8][8];
    #pragma unroll
    for (int i = 0; i < 8; i++)
        #pragma unroll
        for (int j = 0; j < 8; j++)
            acc[i][j] = 0ull;  // {0.f, 0.f}

    for (int k2 = 0; k2 < 64; k2++) {
        unsigned long long xv[8], wv[8];
        #pragma unroll
        for (int i = 0; i < 8; i++) xv[i] = xs[k2 * 128 + ty * 8 + i];
        #pragma unroll
        for (int j = 0; j < 8; j++) wv[j] = ws[k2 * 128 + tx + j * 16];
        #pragma unroll
        for (int i = 0; i < 8; i++)
            #pragma unroll
            for (int j = 0; j < 8; j++)
                acc[i][j] = ffma2(xv[i], wv[j], acc[i][j]);
    }

    // Epilogue: fold the two k-parity partials, add bias, store fp32.
    float bv[8];
    #pragma unroll
    for (int j = 0; j < 8; j++) bv[j] = bias[tx + j * 16];

    #pragma unroll
    for (int i = 0; i < 8; i++) {
        int row = row0 + ty * 8 + i;
        if (row < nrows) {
            #pragma unroll
            for (int j = 0; j < 8; j++) {
                float2 a = *(float2*)&acc[i][j];
                g_support[(size_t)row * HID + (tx + j * 16)] = a.x + a.y + bv[j];
            }
        }
    }
}

// ---------------------------------------------------------------------------
// SpMM: out = A_coo @ support, adj_rows SORTED -> segment by output rows.
// Each block owns rows [r0, r0+RPB); edge range found by binary search.
// No atomics, every output row written exactly once (empty rows get 0).
// ---------------------------------------------------------------------------
__device__ __forceinline__ int lower_bound_dev(const int* __restrict__ a,
                                               int n, int key) {
    int lo = 0, hi = n;
    while (lo < hi) {
        int mid = (lo + hi) >> 1;
        if (__ldg(a + mid) < key) lo = mid + 1; else hi = mid;
    }
    return lo;
}

extern "C" __global__ void __launch_bounds__(128)
spmm_kernel(const int* __restrict__ rows, const int* __restrict__ cols,
            const float* __restrict__ vals, float* __restrict__ out)
{
    const int h  = threadIdx.x;            // column (one per thread, 128B/warp gather)
    const int r0 = blockIdx.x * RPB;

    __shared__ int   s_lo, s_hi;
    __shared__ int   s_r[CH];
    __shared__ int   s_c[CH];
    __shared__ float s_v[CH];

    if (h == 0) {
        s_lo = lower_bound_dev(rows, NNZ_N, r0);
        s_hi = lower_bound_dev(rows, NNZ_N, r0 + RPB);
    }
    __syncthreads();
    const int lo = s_lo, hi = s_hi;

    int   cur = r0;
    float acc = 0.f;

    for (int base = lo; base < hi; base += CH) {
        int cnt = min(CH, hi - base);
        for (int i = h; i < cnt; i += 128) {
            s_r[i] = rows[base + i];
            s_c[i] = cols[base + i];
            s_v[i] = vals[base + i];
        }
        __syncthreads();

        int i = 0;
        // 8-wide batches: all 8 gathers issue before use -> MLP=8/warp.
        for (; i + 8 <= cnt; i += 8) {
            float sv[8], vv[8]; int er[8];
            #pragma unroll
            for (int u = 0; u < 8; u++) {
                er[u] = s_r[i + u];
                vv[u] = s_v[i + u];
                sv[u] = __ldg(&g_support[(size_t)s_c[i + u] * HID + h]);
            }
            #pragma unroll
            for (int u = 0; u < 8; u++) {
                int r = er[u];
                while (cur < r) {           // flush finished row(s); skipped rows -> 0
                    out[(size_t)cur * HID + h] = acc;
                    acc = 0.f; cur++;
                }
                acc = fmaf(vv[u], sv[u], acc);
            }
        }
        for (; i < cnt; i++) {
            int r = s_r[i];
            while (cur < r) {
                out[(size_t)cur * HID + h] = acc;
                acc = 0.f; cur++;
            }
            acc = fmaf(s_v[i], __ldg(&g_support[(size_t)s_c[i] * HID + h]), acc);
        }
        __syncthreads();
    }

    // Tail flush: remaining owned rows (including trailing empty rows).
    const int rend = r0 + RPB;
    while (cur < rend) {
        out[(size_t)cur * HID + h] = acc;
        acc = 0.f; cur++;
    }
}

extern "C" void kernel_launch(void* const* d_in, const int* in_sizes, int n_in,
                              void* d_out, int out_size) {
    const float* X  = (const float*)d_in[0];  // [100000, 128]
    const int*   ar = (const int*)  d_in[1];  // adj_rows (sorted)
    const int*   ac = (const int*)  d_in[2];  // adj_cols
    const float* av = (const float*)d_in[3];  // adj_vals
    const float* W  = (const float*)d_in[4];  // [128, 128] (out, in)
    const float* b  = (const float*)d_in[5];  // [128]
    float* out = (float*)d_out;               // [100000, 128]

    cudaFuncSetAttribute(gemm_kernel,
                         cudaFuncAttributeMaxDynamicSharedMemorySize, 131072);

    int gblocks = (N_ITEMS + 127) / 128;      // 782
    gemm_kernel<<<gblocks, 256, 131072>>>(X, W, b, N_ITEMS);
    spmm_kernel<<<N_ITEMS / RPB, 128>>>(ar, ac, av, out);
}